// round 13
// baseline (speedup 1.0000x reference)
#include <cuda_runtime.h>

#define Nn 50000
#define FIN 128
#define Hd 64
#define NHEADS 4
#define Ed 800000

// ---------------- scratch (static __device__ — no runtime allocation) ----------------
__device__ float g_h0[Nn * Hd];            // x @ W1
__device__ float g_h[Nn * Hd];             // GCN output (relu)
__device__ float g_h2[Nn * Hd];            // GAT output (relu)
__device__ float g_mean[Nn * Hd];          // SAGE mean aggregate
__device__ float g_hg[Nn * NHEADS * Hd];   // h @ Wg   [N,4,64]
__device__ float g_dinv[Nn];               // rsqrt(deg0+1)
__device__ float g_asrc[Nn * NHEADS];
__device__ float g_adst[Nn * NHEADS];
__device__ int   g_row[Ed];                // normalized int32 edge sources
__device__ int   g_col[Ed];                // normalized int32 edge targets
__device__ int   g_is32;                   // dtype flag: 1 if edge_index is int32
__device__ int   g_cnt[Nn];                // in-degree (col0, no loops)
__device__ int   g_off[Nn + 1];            // CSR offsets
__device__ int   g_cur[Nn];                // fill cursors
__device__ int   g_src[Ed];                // CSR: source node per edge, grouped by dst

__device__ __forceinline__ float lrelu02(float v) { return v > 0.f ? v : 0.2f * v; }
__device__ __forceinline__ int clampN(int v) { return v < 0 ? 0 : (v >= Nn ? Nn - 1 : v); }

// ---------------- edge dtype detect + normalize ----------------
// Reading the first Ed int64 slots is bounds-safe for both dtypes:
// int32 buffer (2*Ed int32 = Ed int64-sized slots) and int64 buffer (2*Ed slots).
__global__ void k_detect(const long long* __restrict__ ei) {
    int e = blockIdx.x * blockDim.x + threadIdx.x;
    if (e >= Ed) return;
    long long v = ei[e];
    if (v < 0 || v >= (long long)Nn) atomicOr(&g_is32, 1);
}

__global__ void k_convert(const void* __restrict__ eiv) {
    int e = blockIdx.x * blockDim.x + threadIdx.x;
    if (e >= Ed) return;
    int r, c;
    if (g_is32) {
        const int* p = (const int*)eiv;
        r = p[e]; c = p[Ed + e];
    } else {
        const long long* p = (const long long*)eiv;
        r = (int)p[e]; c = (int)p[Ed + e];
    }
    g_row[e] = clampN(r);
    g_col[e] = clampN(c);
}

// ---------------- CSR build ----------------
__global__ void k_zero() {
    int i = blockIdx.x * blockDim.x + threadIdx.x;
    if (i == 0) g_is32 = 0;   // runs BEFORE k_detect in stream order
    if (i < Nn) g_cnt[i] = 0;
}

__global__ void k_hist() {
    int e = blockIdx.x * blockDim.x + threadIdx.x;
    if (e < Ed) atomicAdd(&g_cnt[g_col[e]], 1);
}

// single-block exclusive prefix scan over g_cnt -> g_off/g_cur (1024 threads)
__global__ void k_scan() {
    __shared__ int wsum[32];
    __shared__ int carry;
    int t = threadIdx.x, lane = t & 31, w = t >> 5;
    if (t == 0) carry = 0;
    __syncthreads();
    for (int base = 0; base < Nn; base += 1024) {
        int i = base + t;
        int v = (i < Nn) ? g_cnt[i] : 0;
        int x = v;
#pragma unroll
        for (int off = 1; off < 32; off <<= 1) {
            int y = __shfl_up_sync(0xffffffffu, x, off);
            if (lane >= off) x += y;
        }
        if (lane == 31) wsum[w] = x;
        __syncthreads();
        if (w == 0) {
            int s = wsum[lane];
#pragma unroll
            for (int off = 1; off < 32; off <<= 1) {
                int y = __shfl_up_sync(0xffffffffu, s, off);
                if (lane >= off) s += y;
            }
            wsum[lane] = s;   // inclusive scan of warp totals
        }
        __syncthreads();
        int wex = (w == 0) ? 0 : wsum[w - 1];
        int excl = carry + wex + x - v;
        if (i < Nn) { g_off[i] = excl; g_cur[i] = excl; }
        __syncthreads();
        if (t == 1023) carry += wsum[31];
        __syncthreads();
    }
    if (t == 0) g_off[Nn] = carry;
}

__global__ void k_fill() {
    int e = blockIdx.x * blockDim.x + threadIdx.x;
    if (e >= Ed) return;
    int pos = atomicAdd(&g_cur[g_col[e]], 1);
    if (pos >= 0 && pos < Ed) g_src[pos] = g_row[e];
}

__global__ void k_dinv() {
    int i = blockIdx.x * blockDim.x + threadIdx.x;
    if (i < Nn) g_dinv[i] = rsqrtf((float)g_cnt[i] + 1.0f);
}

// ---------------- GEMMs ----------------
// h0 = x @ W1   [N,128]@[128,64]; 4 nodes / 256-thread block
__global__ void k_gemm1(const float* __restrict__ x, const float* __restrict__ W1) {
    __shared__ float xs[4][FIN];
    int slot = threadIdx.x >> 6, t = threadIdx.x & 63;
    int n0 = blockIdx.x * 4;
    int li = threadIdx.x;
#pragma unroll
    for (int k = 0; k < 2; k++) {
        int idx = li + k * 256;                 // 0..511
        int s = idx >> 7, c = idx & 127;
        int n = n0 + s;
        xs[s][c] = (n < Nn) ? x[n * FIN + c] : 0.f;
    }
    __syncthreads();
    int n = n0 + slot;
    if (n >= Nn) return;
    float acc = 0.f;
#pragma unroll
    for (int k = 0; k < FIN; k++) acc = fmaf(xs[slot][k], W1[k * Hd + t], acc);
    g_h0[n * Hd + t] = acc;
}

// hg = h @ Wg  [N,64]@[64,256], fused attention logit reduction
__global__ void k_gemmg(const float* __restrict__ Wg,
                        const float* __restrict__ att_src, const float* __restrict__ att_dst) {
    __shared__ float hs[Hd];
    __shared__ float ssrc[8], sdst[8];
    int n = blockIdx.x, t = threadIdx.x;          // 256 threads
    if (t < Hd) hs[t] = g_h[n * Hd + t];
    __syncthreads();
    float acc = 0.f;
#pragma unroll
    for (int k = 0; k < Hd; k++) acc = fmaf(hs[k], Wg[k * (NHEADS * Hd) + t], acc);
    g_hg[n * (NHEADS * Hd) + t] = acc;
    int h = t >> 6, c = t & 63;
    float ps = acc * att_src[h * Hd + c];
    float pd = acc * att_dst[h * Hd + c];
#pragma unroll
    for (int off = 16; off > 0; off >>= 1) {
        ps += __shfl_xor_sync(0xffffffffu, ps, off);
        pd += __shfl_xor_sync(0xffffffffu, pd, off);
    }
    int w = t >> 5;
    if ((t & 31) == 0) { ssrc[w] = ps; sdst[w] = pd; }
    __syncthreads();
    if (t < NHEADS) {
        g_asrc[n * NHEADS + t] = ssrc[2 * t] + ssrc[2 * t + 1];
        g_adst[n * NHEADS + t] = sdst[2 * t] + sdst[2 * t + 1];
    }
}

// ---------------- GCN: warp-per-node pull + finalize ----------------
__global__ void k_gcn(const float* __restrict__ b1) {
    int node = (blockIdx.x * blockDim.x + threadIdx.x) >> 5;
    int lane = threadIdx.x & 31;
    if (node >= Nn) return;
    int s = g_off[node], e = g_off[node + 1];
    float dc = g_dinv[node];
    float a0 = 0.f, a1 = 0.f;
    for (int j = s; j < e; j++) {
        int r = g_src[j];
        float w = dc * g_dinv[r];
        a0 = fmaf(w, g_h0[r * Hd + lane], a0);
        a1 = fmaf(w, g_h0[r * Hd + 32 + lane], a1);
    }
    float dd = dc * dc;
    a0 = fmaf(dd, g_h0[node * Hd + lane], a0) + b1[lane];
    a1 = fmaf(dd, g_h0[node * Hd + 32 + lane], a1) + b1[32 + lane];
    g_h[node * Hd + lane]      = fmaxf(a0, 0.f);
    g_h[node * Hd + 32 + lane] = fmaxf(a1, 0.f);
}

// ---------------- GAT: warp-per-node, fused softmax + aggregation ----------------
__global__ void k_gat(const float* __restrict__ bg) {
    int node = (blockIdx.x * blockDim.x + threadIdx.x) >> 5;
    int lane = threadIdx.x & 31;
    if (node >= Nn) return;
    int c = node;
    int s = g_off[c], e = g_off[c + 1];
    float4 adv = *(const float4*)&g_adst[c * NHEADS];
    float ad[4] = {adv.x, adv.y, adv.z, adv.w};
    float4 asv = *(const float4*)&g_asrc[c * NHEADS];
    float self_l[4];
    float m[4];
#pragma unroll
    for (int h = 0; h < 4; h++) {
        float av = (h == 0) ? asv.x : (h == 1) ? asv.y : (h == 2) ? asv.z : asv.w;
        self_l[h] = lrelu02(av + ad[h]);
        m[h] = self_l[h];
    }
    // pass 1: segment max (lanes strided over edges)
    for (int j = s + lane; j < e; j += 32) {
        int r = g_src[j];
        float4 av4 = *(const float4*)&g_asrc[r * NHEADS];
        float a4[4] = {av4.x, av4.y, av4.z, av4.w};
#pragma unroll
        for (int h = 0; h < 4; h++) m[h] = fmaxf(m[h], lrelu02(a4[h] + ad[h]));
    }
#pragma unroll
    for (int off = 16; off > 0; off >>= 1)
#pragma unroll
        for (int h = 0; h < 4; h++)
            m[h] = fmaxf(m[h], __shfl_xor_sync(0xffffffffu, m[h], off));
    // pass 2: denom
    float den[4];
#pragma unroll
    for (int h = 0; h < 4; h++) den[h] = (lane == 0) ? __expf(self_l[h] - m[h]) : 0.f;
    for (int j = s + lane; j < e; j += 32) {
        int r = g_src[j];
        float4 av4 = *(const float4*)&g_asrc[r * NHEADS];
        float a4[4] = {av4.x, av4.y, av4.z, av4.w};
#pragma unroll
        for (int h = 0; h < 4; h++) den[h] += __expf(lrelu02(a4[h] + ad[h]) - m[h]);
    }
#pragma unroll
    for (int off = 16; off > 0; off >>= 1)
#pragma unroll
        for (int h = 0; h < 4; h++)
            den[h] += __shfl_xor_sync(0xffffffffu, den[h], off);
#pragma unroll
    for (int h = 0; h < 4; h++) den[h] = 1.f / den[h];
    // pass 3: weighted aggregation (whole warp per edge; broadcast alpha)
    float acc[8] = {0.f, 0.f, 0.f, 0.f, 0.f, 0.f, 0.f, 0.f};
    for (int j = s; j < e; j++) {
        int r = g_src[j];
        float4 av4 = *(const float4*)&g_asrc[r * NHEADS];
        float a4[4] = {av4.x, av4.y, av4.z, av4.w};
#pragma unroll
        for (int h = 0; h < 4; h++) {
            float al = __expf(lrelu02(a4[h] + ad[h]) - m[h]) * den[h];
            const float* hb = &g_hg[(r * NHEADS + h) * Hd];
            acc[2 * h]     = fmaf(al, hb[lane], acc[2 * h]);
            acc[2 * h + 1] = fmaf(al, hb[lane + 32], acc[2 * h + 1]);
        }
    }
    // self edge
#pragma unroll
    for (int h = 0; h < 4; h++) {
        float al = __expf(self_l[h] - m[h]) * den[h];
        const float* hb = &g_hg[(c * NHEADS + h) * Hd];
        acc[2 * h]     = fmaf(al, hb[lane], acc[2 * h]);
        acc[2 * h + 1] = fmaf(al, hb[lane + 32], acc[2 * h + 1]);
    }
    float o0 = 0.25f * (acc[0] + acc[2] + acc[4] + acc[6]);
    float o1 = 0.25f * (acc[1] + acc[3] + acc[5] + acc[7]);
    g_h2[c * Hd + lane]      = fmaxf(o0 + bg[lane], 0.f);
    g_h2[c * Hd + 32 + lane] = fmaxf(o1 + bg[32 + lane], 0.f);
}

// ---------------- SAGE mean aggregation: warp-per-node ----------------
__global__ void k_sage() {
    int node = (blockIdx.x * blockDim.x + threadIdx.x) >> 5;
    int lane = threadIdx.x & 31;
    if (node >= Nn) return;
    int s = g_off[node], e = g_off[node + 1];
    float a0 = 0.f, a1 = 0.f;
    for (int j = s; j < e; j++) {
        int r = g_src[j];
        a0 += g_h2[r * Hd + lane];
        a1 += g_h2[r * Hd + 32 + lane];
    }
    float inv = 1.f / fmaxf((float)(e - s), 1.f);
    g_mean[node * Hd + lane]      = a0 * inv;
    g_mean[node * Hd + 32 + lane] = a1 * inv;
}

// emb = mean @ Wl + bl + h2 @ Wr ; 4 nodes / 256-thread block
__global__ void k_sage_fin(const float* __restrict__ Wl, const float* __restrict__ bl,
                           const float* __restrict__ Wr, float* __restrict__ out) {
    __shared__ float ms[4][Hd], hs[4][Hd];
    int slot = threadIdx.x >> 6, t = threadIdx.x & 63;
    int n = blockIdx.x * 4 + slot;
    if (n < Nn) {
        ms[slot][t] = g_mean[n * Hd + t];
        hs[slot][t] = g_h2[n * Hd + t];
    }
    __syncthreads();
    if (n >= Nn) return;
    float acc = bl[t];
#pragma unroll
    for (int k = 0; k < Hd; k++) {
        acc = fmaf(ms[slot][k], Wl[k * Hd + t], acc);
        acc = fmaf(hs[slot][k], Wr[k * Hd + t], acc);
    }
    out[n * Hd + t] = acc;
}

// anomaly / risk heads; 4 nodes / 256-thread block, warp pairs per node
__global__ void k_heads(const float* __restrict__ a1w, const float* __restrict__ a1b,
                        const float* __restrict__ a2w, const float* __restrict__ a2b,
                        const float* __restrict__ r1w, const float* __restrict__ r1b,
                        const float* __restrict__ r2w, const float* __restrict__ r2b,
                        float* __restrict__ out) {
    __shared__ float es[4][Hd];
    int slot = threadIdx.x >> 6, t = threadIdx.x & 63;
    int n = blockIdx.x * 4 + slot;
    if (n < Nn) es[slot][t] = out[n * Hd + t];
    __syncthreads();
    if (n >= Nn) return;
    int j = t & 31;
    bool an = t < 32;
    const float* w1 = an ? a1w : r1w;
    const float* b1 = an ? a1b : r1b;
    const float* w2 = an ? a2w : r2w;
    float b2 = an ? a2b[0] : r2b[0];
    float u = b1[j];
#pragma unroll
    for (int k = 0; k < Hd; k++) u = fmaf(es[slot][k], w1[k * 32 + j], u);
    u = fmaxf(u, 0.f);
    float ctr = u * w2[j];
#pragma unroll
    for (int off = 16; off > 0; off >>= 1)
        ctr += __shfl_xor_sync(0xffffffffu, ctr, off);
    if (j == 0) {
        float z = ctr + b2;
        out[Nn * Hd + (an ? 0 : Nn) + n] = 1.f / (1.f + __expf(-z));
    }
}

// ---------------- launch ----------------
extern "C" void kernel_launch(void* const* d_in, const int* in_sizes, int n_in,
                              void* d_out, int out_size) {
    const float* x  = (const float*)d_in[0];
    const void*  ei = d_in[1];
    const float* W1 = (const float*)d_in[2];
    const float* b1 = (const float*)d_in[3];
    const float* Wg = (const float*)d_in[4];
    const float *att_src, *att_dst, *bg;
    if (in_sizes[5] == NHEADS * Hd) {   // dict order: att_src, att_dst, bg
        att_src = (const float*)d_in[5]; att_dst = (const float*)d_in[6]; bg = (const float*)d_in[7];
    } else {                            // signature order: bg, att_src, att_dst
        bg = (const float*)d_in[5]; att_src = (const float*)d_in[6]; att_dst = (const float*)d_in[7];
    }
    const float* Wl  = (const float*)d_in[8];
    const float* bl  = (const float*)d_in[9];
    const float* Wr  = (const float*)d_in[10];
    const float* a1w = (const float*)d_in[11];
    const float* a1b = (const float*)d_in[12];
    const float* a2w = (const float*)d_in[13];
    const float* a2b = (const float*)d_in[14];
    const float* r1w = (const float*)d_in[15];
    const float* r1b = (const float*)d_in[16];
    const float* r2w = (const float*)d_in[17];
    const float* r2b = (const float*)d_in[18];
    float* out = (float*)d_out;

    const int warpsPerBlk = 8;                       // 256 threads
    const int nodeGrid = (Nn + warpsPerBlk - 1) / warpsPerBlk;

    k_zero<<<(Nn + 255) / 256, 256>>>();
    k_detect<<<(Ed + 255) / 256, 256>>>((const long long*)ei);
    k_convert<<<(Ed + 255) / 256, 256>>>(ei);
    k_hist<<<(Ed + 255) / 256, 256>>>();
    k_scan<<<1, 1024>>>();
    k_fill<<<(Ed + 255) / 256, 256>>>();
    k_dinv<<<(Nn + 255) / 256, 256>>>();
    k_gemm1<<<(Nn + 3) / 4, 256>>>(x, W1);
    k_gcn<<<nodeGrid, 256>>>(b1);
    k_gemmg<<<Nn, 256>>>(Wg, att_src, att_dst);
    k_gat<<<nodeGrid, 256>>>(bg);
    k_sage<<<nodeGrid, 256>>>();
    k_sage_fin<<<(Nn + 3) / 4, 256>>>(Wl, bl, Wr, out);
    k_heads<<<(Nn + 3) / 4, 256>>>(a1w, a1b, a2w, a2b, r1w, r1b, r2w, r2b, out);
}

// round 14
// speedup vs baseline: 1.3204x; 1.3204x over previous
#include <cuda_runtime.h>

#define Nn 50000
#define FIN 128
#define Hd 64
#define NHEADS 4
#define Ed 800000

// ---------------- scratch ----------------
__device__ float g_h0[Nn * Hd];
__device__ float g_h[Nn * Hd];
__device__ float g_h2[Nn * Hd];
__device__ float g_mean[Nn * Hd];
__device__ float g_hg[Nn * NHEADS * Hd];
__device__ float g_dinv[Nn];
__device__ float g_asrc[Nn * NHEADS];
__device__ float g_adst[Nn * NHEADS];
__device__ int   g_row[Ed];
__device__ int   g_col[Ed];
__device__ int   g_is32;
__device__ int   g_cnt[Nn];
__device__ int   g_off[Nn + 1];
__device__ int   g_cur[Nn];
__device__ int   g_src[Ed];

__device__ __forceinline__ float lrelu02(float v) { return v > 0.f ? v : 0.2f * v; }
__device__ __forceinline__ int clampN(int v) { return v < 0 ? 0 : (v >= Nn ? Nn - 1 : v); }

// ---------------- edge dtype detect + normalize (UNCHANGED — proven) ----------------
__global__ void k_detect(const long long* __restrict__ ei) {
    int e = blockIdx.x * blockDim.x + threadIdx.x;
    if (e >= Ed) return;
    long long v = ei[e];
    if (v < 0 || v >= (long long)Nn) atomicOr(&g_is32, 1);
}

__global__ void k_convert(const void* __restrict__ eiv) {
    int e = blockIdx.x * blockDim.x + threadIdx.x;
    if (e >= Ed) return;
    int r, c;
    if (g_is32) {
        const int* p = (const int*)eiv;
        r = p[e]; c = p[Ed + e];
    } else {
        const long long* p = (const long long*)eiv;
        r = (int)p[e]; c = (int)p[Ed + e];
    }
    g_row[e] = clampN(r);
    g_col[e] = clampN(c);
}

// ---------------- CSR build (UNCHANGED) ----------------
__global__ void k_zero() {
    int i = blockIdx.x * blockDim.x + threadIdx.x;
    if (i == 0) g_is32 = 0;
    if (i < Nn) g_cnt[i] = 0;
}

__global__ void k_hist() {
    int e = blockIdx.x * blockDim.x + threadIdx.x;
    if (e < Ed) atomicAdd(&g_cnt[g_col[e]], 1);
}

__global__ void k_scan() {
    __shared__ int wsum[32];
    __shared__ int carry;
    int t = threadIdx.x, lane = t & 31, w = t >> 5;
    if (t == 0) carry = 0;
    __syncthreads();
    for (int base = 0; base < Nn; base += 1024) {
        int i = base + t;
        int v = (i < Nn) ? g_cnt[i] : 0;
        int x = v;
#pragma unroll
        for (int off = 1; off < 32; off <<= 1) {
            int y = __shfl_up_sync(0xffffffffu, x, off);
            if (lane >= off) x += y;
        }
        if (lane == 31) wsum[w] = x;
        __syncthreads();
        if (w == 0) {
            int s = wsum[lane];
#pragma unroll
            for (int off = 1; off < 32; off <<= 1) {
                int y = __shfl_up_sync(0xffffffffu, s, off);
                if (lane >= off) s += y;
            }
            wsum[lane] = s;
        }
        __syncthreads();
        int wex = (w == 0) ? 0 : wsum[w - 1];
        int excl = carry + wex + x - v;
        if (i < Nn) { g_off[i] = excl; g_cur[i] = excl; }
        __syncthreads();
        if (t == 1023) carry += wsum[31];
        __syncthreads();
    }
    if (t == 0) g_off[Nn] = carry;
}

__global__ void k_fill() {
    int e = blockIdx.x * blockDim.x + threadIdx.x;
    if (e >= Ed) return;
    int pos = atomicAdd(&g_cur[g_col[e]], 1);
    if (pos >= 0 && pos < Ed) g_src[pos] = g_row[e];
}

__global__ void k_dinv() {
    int i = blockIdx.x * blockDim.x + threadIdx.x;
    if (i < Nn) g_dinv[i] = rsqrtf((float)g_cnt[i] + 1.0f);
}

// ---------------- GEMM 1: h0 = x @ W1, TILED 32 nodes/block ----------------
__global__ void k_gemm1(const float* __restrict__ x, const float* __restrict__ W1) {
    __shared__ float xs[32][FIN];
    int tid = threadIdx.x;                       // 256
    int n0 = blockIdx.x * 32;
    // load 32 x-rows (4096 floats)
#pragma unroll
    for (int i = 0; i < 16; i++) {
        int idx = tid + i * 256;
        int s = idx >> 7, c = idx & 127;
        int n = n0 + s;
        xs[s][c] = (n < Nn) ? x[n * FIN + c] : 0.f;
    }
    __syncthreads();
    int t = tid & 63, slot = tid >> 6;           // thread computes col t for 8 nodes
    float acc[8] = {0,0,0,0,0,0,0,0};
    for (int k = 0; k < FIN; k++) {
        float w = W1[k * Hd + t];
#pragma unroll
        for (int i = 0; i < 8; i++)
            acc[i] = fmaf(xs[slot * 8 + i][k], w, acc[i]);
    }
#pragma unroll
    for (int i = 0; i < 8; i++) {
        int n = n0 + slot * 8 + i;
        if (n < Nn) g_h0[n * Hd + t] = acc[i];
    }
}

// ---------------- GCN: warp-per-node pull (float2) ----------------
__global__ void k_gcn(const float* __restrict__ b1) {
    int node = (blockIdx.x * blockDim.x + threadIdx.x) >> 5;
    int lane = threadIdx.x & 31;
    if (node >= Nn) return;
    int s = g_off[node], e = g_off[node + 1];
    float dc = g_dinv[node];
    float2 a = make_float2(0.f, 0.f);
    for (int j = s; j < e; j++) {
        int r = g_src[j];
        float w = dc * g_dinv[r];
        float2 v = *(const float2*)&g_h0[r * Hd + lane * 2];
        a.x = fmaf(w, v.x, a.x);
        a.y = fmaf(w, v.y, a.y);
    }
    float dd = dc * dc;
    float2 sv = *(const float2*)&g_h0[node * Hd + lane * 2];
    float2 bv = *(const float2*)&b1[lane * 2];
    a.x = fmaf(dd, sv.x, a.x) + bv.x;
    a.y = fmaf(dd, sv.y, a.y) + bv.y;
    float2 o = make_float2(fmaxf(a.x, 0.f), fmaxf(a.y, 0.f));
    *(float2*)&g_h[node * Hd + lane * 2] = o;
}

// ---------------- GEMM G: hg = h @ Wg, TILED 32 nodes/block, fused att logits ----------------
__global__ void k_gemmg(const float* __restrict__ Wg,
                        const float* __restrict__ att_src, const float* __restrict__ att_dst) {
    __shared__ float hs[32][Hd];
    __shared__ float ssrc[32][8], sdst[32][8];
    int tid = threadIdx.x;                       // 256 = output column
    int n0 = blockIdx.x * 32;
    int lane = tid & 31, w = tid >> 5;
#pragma unroll
    for (int i = 0; i < 8; i++) {
        int idx = tid + i * 256;
        int s = idx >> 6, c = idx & 63;
        int n = n0 + s;
        hs[s][c] = (n < Nn) ? g_h[n * Hd + c] : 0.f;
    }
    __syncthreads();
    float acc[32];
#pragma unroll
    for (int n = 0; n < 32; n++) acc[n] = 0.f;
    for (int k = 0; k < Hd; k++) {
        float wv = Wg[k * (NHEADS * Hd) + tid];
#pragma unroll
        for (int n = 0; n < 32; n++)
            acc[n] = fmaf(hs[n][k], wv, acc[n]);
    }
    // store hg
#pragma unroll
    for (int n = 0; n < 32; n++) {
        int nn = n0 + n;
        if (nn < Nn) g_hg[nn * (NHEADS * Hd) + tid] = acc[n];
    }
    // attention pieces: thread tid = h*64+c  -> att_src[tid]
    float as_t = att_src[tid];
    float ad_t = att_dst[tid];
#pragma unroll
    for (int n = 0; n < 32; n++) {
        float ps = acc[n] * as_t;
        float pd = acc[n] * ad_t;
#pragma unroll
        for (int off = 16; off > 0; off >>= 1) {
            ps += __shfl_xor_sync(0xffffffffu, ps, off);
            pd += __shfl_xor_sync(0xffffffffu, pd, off);
        }
        if (lane == 0) { ssrc[n][w] = ps; sdst[n][w] = pd; }
    }
    __syncthreads();
    if (tid < 128) {
        int n = tid >> 2, h = tid & 3;
        int nn = n0 + n;
        if (nn < Nn) {
            g_asrc[nn * NHEADS + h] = ssrc[n][2 * h] + ssrc[n][2 * h + 1];
            g_adst[nn * NHEADS + h] = sdst[n][2 * h] + sdst[n][2 * h + 1];
        }
    }
}

// ---------------- GAT: warp-per-node, float4 pass 3 ----------------
__global__ void k_gat(const float* __restrict__ bg) {
    int node = (blockIdx.x * blockDim.x + threadIdx.x) >> 5;
    int lane = threadIdx.x & 31;
    if (node >= Nn) return;
    int c = node;
    int s = g_off[c], e = g_off[c + 1];
    float4 adv = *(const float4*)&g_adst[c * NHEADS];
    float ad[4] = {adv.x, adv.y, adv.z, adv.w};
    float4 asv = *(const float4*)&g_asrc[c * NHEADS];
    float self_l[4], m[4];
#pragma unroll
    for (int h = 0; h < 4; h++) {
        float av = (h == 0) ? asv.x : (h == 1) ? asv.y : (h == 2) ? asv.z : asv.w;
        self_l[h] = lrelu02(av + ad[h]);
        m[h] = self_l[h];
    }
    // pass 1: segment max (lane-strided)
    for (int j = s + lane; j < e; j += 32) {
        int r = g_src[j];
        float4 av4 = *(const float4*)&g_asrc[r * NHEADS];
        float a4[4] = {av4.x, av4.y, av4.z, av4.w};
#pragma unroll
        for (int h = 0; h < 4; h++) m[h] = fmaxf(m[h], lrelu02(a4[h] + ad[h]));
    }
#pragma unroll
    for (int off = 16; off > 0; off >>= 1)
#pragma unroll
        for (int h = 0; h < 4; h++)
            m[h] = fmaxf(m[h], __shfl_xor_sync(0xffffffffu, m[h], off));
    // pass 2: denom
    float den[4];
#pragma unroll
    for (int h = 0; h < 4; h++) den[h] = (lane == 0) ? __expf(self_l[h] - m[h]) : 0.f;
    for (int j = s + lane; j < e; j += 32) {
        int r = g_src[j];
        float4 av4 = *(const float4*)&g_asrc[r * NHEADS];
        float a4[4] = {av4.x, av4.y, av4.z, av4.w};
#pragma unroll
        for (int h = 0; h < 4; h++) den[h] += __expf(lrelu02(a4[h] + ad[h]) - m[h]);
    }
#pragma unroll
    for (int off = 16; off > 0; off >>= 1)
#pragma unroll
        for (int h = 0; h < 4; h++)
            den[h] += __shfl_xor_sync(0xffffffffu, den[h], off);
#pragma unroll
    for (int h = 0; h < 4; h++) den[h] = 1.f / den[h];
    // pass 3: float4 loads — lane covers head hA (0/1) and hB (2/3), cols (lane&15)*4..+3
    int hA = lane >> 4;       // 0|1
    int hB = 2 + hA;          // 2|3
    float4 accA = make_float4(0.f, 0.f, 0.f, 0.f);
    float4 accB = make_float4(0.f, 0.f, 0.f, 0.f);
    for (int j = s; j < e; j++) {
        int r = g_src[j];
        float4 av4 = *(const float4*)&g_asrc[r * NHEADS];
        float a4[4] = {av4.x, av4.y, av4.z, av4.w};
        float alA = __expf(lrelu02(a4[hA] + ad[hA]) - m[hA]) * den[hA];
        float alB = __expf(lrelu02(a4[hB] + ad[hB]) - m[hB]) * den[hB];
        float4 va = *(const float4*)&g_hg[r * 256 + lane * 4];
        float4 vb = *(const float4*)&g_hg[r * 256 + 128 + lane * 4];
        accA.x = fmaf(alA, va.x, accA.x); accA.y = fmaf(alA, va.y, accA.y);
        accA.z = fmaf(alA, va.z, accA.z); accA.w = fmaf(alA, va.w, accA.w);
        accB.x = fmaf(alB, vb.x, accB.x); accB.y = fmaf(alB, vb.y, accB.y);
        accB.z = fmaf(alB, vb.z, accB.z); accB.w = fmaf(alB, vb.w, accB.w);
    }
    // self edge
    {
        float alA = __expf(self_l[hA] - m[hA]) * den[hA];
        float alB = __expf(self_l[hB] - m[hB]) * den[hB];
        float4 va = *(const float4*)&g_hg[c * 256 + lane * 4];
        float4 vb = *(const float4*)&g_hg[c * 256 + 128 + lane * 4];
        accA.x = fmaf(alA, va.x, accA.x); accA.y = fmaf(alA, va.y, accA.y);
        accA.z = fmaf(alA, va.z, accA.z); accA.w = fmaf(alA, va.w, accA.w);
        accB.x = fmaf(alB, vb.x, accB.x); accB.y = fmaf(alB, vb.y, accB.y);
        accB.z = fmaf(alB, vb.z, accB.z); accB.w = fmaf(alB, vb.w, accB.w);
    }
    // combine heads across lane^16 pairs
    float4 tot;
    tot.x = accA.x + __shfl_xor_sync(0xffffffffu, accA.x, 16)
          + accB.x + __shfl_xor_sync(0xffffffffu, accB.x, 16);
    tot.y = accA.y + __shfl_xor_sync(0xffffffffu, accA.y, 16)
          + accB.y + __shfl_xor_sync(0xffffffffu, accB.y, 16);
    tot.z = accA.z + __shfl_xor_sync(0xffffffffu, accA.z, 16)
          + accB.z + __shfl_xor_sync(0xffffffffu, accB.z, 16);
    tot.w = accA.w + __shfl_xor_sync(0xffffffffu, accA.w, 16)
          + accB.w + __shfl_xor_sync(0xffffffffu, accB.w, 16);
    if (lane < 16) {
        float4 bgv = *(const float4*)&bg[lane * 4];
        float4 o;
        o.x = fmaxf(0.25f * tot.x + bgv.x, 0.f);
        o.y = fmaxf(0.25f * tot.y + bgv.y, 0.f);
        o.z = fmaxf(0.25f * tot.z + bgv.z, 0.f);
        o.w = fmaxf(0.25f * tot.w + bgv.w, 0.f);
        *(float4*)&g_h2[c * Hd + lane * 4] = o;
    }
}

// ---------------- SAGE mean: warp-per-node (float2) ----------------
__global__ void k_sage() {
    int node = (blockIdx.x * blockDim.x + threadIdx.x) >> 5;
    int lane = threadIdx.x & 31;
    if (node >= Nn) return;
    int s = g_off[node], e = g_off[node + 1];
    float2 a = make_float2(0.f, 0.f);
    for (int j = s; j < e; j++) {
        int r = g_src[j];
        float2 v = *(const float2*)&g_h2[r * Hd + lane * 2];
        a.x += v.x; a.y += v.y;
    }
    float inv = 1.f / fmaxf((float)(e - s), 1.f);
    float2 o = make_float2(a.x * inv, a.y * inv);
    *(float2*)&g_mean[node * Hd + lane * 2] = o;
}

// ---------------- fused: emb = mean@Wl + bl + h2@Wr  ->  out + both heads ----------------
// TILED 32 nodes/block, 256 threads
__global__ void k_out(const float* __restrict__ Wl, const float* __restrict__ bl,
                      const float* __restrict__ Wr,
                      const float* __restrict__ a1w, const float* __restrict__ a1b,
                      const float* __restrict__ a2w, const float* __restrict__ a2b,
                      const float* __restrict__ r1w, const float* __restrict__ r1b,
                      const float* __restrict__ r2w, const float* __restrict__ r2b,
                      float* __restrict__ out) {
    __shared__ float ms[32][Hd];
    __shared__ float hs2[32][Hd];
    int tid = threadIdx.x;
    int n0 = blockIdx.x * 32;
#pragma unroll
    for (int i = 0; i < 8; i++) {
        int idx = tid + i * 256;
        int s = idx >> 6, c = idx & 63;
        int n = n0 + s;
        ms[s][c]  = (n < Nn) ? g_mean[n * Hd + c] : 0.f;
        hs2[s][c] = (n < Nn) ? g_h2[n * Hd + c]   : 0.f;
    }
    __syncthreads();
    int t = tid & 63, slot = tid >> 6;           // col t, 8 nodes per thread
    float acc[8];
    float blv = bl[t];
#pragma unroll
    for (int i = 0; i < 8; i++) acc[i] = blv;
    for (int k = 0; k < Hd; k++) {
        float wl = Wl[k * Hd + t];
        float wr = Wr[k * Hd + t];
#pragma unroll
        for (int i = 0; i < 8; i++) {
            int ln = slot * 8 + i;
            acc[i] = fmaf(ms[ln][k], wl, acc[i]);
            acc[i] = fmaf(hs2[ln][k], wr, acc[i]);
        }
    }
#pragma unroll
    for (int i = 0; i < 8; i++) {
        int n = n0 + slot * 8 + i;
        if (n < Nn) out[n * Hd + t] = acc[i];
    }
    __syncthreads();                              // ms reads done; reuse ms as emb store
#pragma unroll
    for (int i = 0; i < 8; i++) ms[slot * 8 + i][t] = acc[i];
    __syncthreads();
    // heads: warp w -> head = w&1, node group = w>>2... (8 warps = 2 heads x 4 groups)
    int w = tid >> 5, lane = tid & 31;
    int head = w & 1, grp = w >> 1;              // grp 0..3 -> nodes grp*8..+7
    const float* w1 = head ? r1w : a1w;
    const float* b1 = head ? r1b : a1b;
    const float* w2 = head ? r2w : a2w;
    float b2 = head ? r2b[0] : a2b[0];
    float b1v = b1[lane];
    float w2v = w2[lane];
    float u[8];
#pragma unroll
    for (int i = 0; i < 8; i++) u[i] = b1v;
    for (int k = 0; k < Hd; k++) {
        float wv = w1[k * 32 + lane];
#pragma unroll
        for (int i = 0; i < 8; i++)
            u[i] = fmaf(ms[grp * 8 + i][k], wv, u[i]);
    }
#pragma unroll
    for (int i = 0; i < 8; i++) {
        float ctr = fmaxf(u[i], 0.f) * w2v;
#pragma unroll
        for (int off = 16; off > 0; off >>= 1)
            ctr += __shfl_xor_sync(0xffffffffu, ctr, off);
        if (lane == 0) {
            int n = n0 + grp * 8 + i;
            if (n < Nn) {
                float z = ctr + b2;
                out[Nn * Hd + (head ? Nn : 0) + n] = 1.f / (1.f + __expf(-z));
            }
        }
    }
}

// ---------------- launch ----------------
extern "C" void kernel_launch(void* const* d_in, const int* in_sizes, int n_in,
                              void* d_out, int out_size) {
    const float* x  = (const float*)d_in[0];
    const void*  ei = d_in[1];
    const float* W1 = (const float*)d_in[2];
    const float* b1 = (const float*)d_in[3];
    const float* Wg = (const float*)d_in[4];
    const float *att_src, *att_dst, *bg;
    if (in_sizes[5] == NHEADS * Hd) {
        att_src = (const float*)d_in[5]; att_dst = (const float*)d_in[6]; bg = (const float*)d_in[7];
    } else {
        bg = (const float*)d_in[5]; att_src = (const float*)d_in[6]; att_dst = (const float*)d_in[7];
    }
    const float* Wl  = (const float*)d_in[8];
    const float* bl  = (const float*)d_in[9];
    const float* Wr  = (const float*)d_in[10];
    const float* a1w = (const float*)d_in[11];
    const float* a1b = (const float*)d_in[12];
    const float* a2w = (const float*)d_in[13];
    const float* a2b = (const float*)d_in[14];
    const float* r1w = (const float*)d_in[15];
    const float* r1b = (const float*)d_in[16];
    const float* r2w = (const float*)d_in[17];
    const float* r2b = (const float*)d_in[18];
    float* out = (float*)d_out;

    const int nodeGrid = (Nn + 7) / 8;            // warp-per-node, 8 warps/block
    const int tileGrid = (Nn + 31) / 32;          // 32-node GEMM tiles

    k_zero<<<(Nn + 255) / 256, 256>>>();
    k_detect<<<(Ed + 255) / 256, 256>>>((const long long*)ei);
    k_convert<<<(Ed + 255) / 256, 256>>>(ei);
    k_hist<<<(Ed + 255) / 256, 256>>>();
    k_scan<<<1, 1024>>>();
    k_fill<<<(Ed + 255) / 256, 256>>>();
    k_dinv<<<(Nn + 255) / 256, 256>>>();
    k_gemm1<<<tileGrid, 256>>>(x, W1);
    k_gcn<<<nodeGrid, 256>>>(b1);
    k_gemmg<<<tileGrid, 256>>>(Wg, att_src, att_dst);
    k_gat<<<nodeGrid, 256>>>(bg);
    k_sage<<<nodeGrid, 256>>>();
    k_out<<<tileGrid, 256>>>(Wl, bl, Wr, a1w, a1b, a2w, a2b, r1w, r1b, r2w, r2b, out);
}